// round 5
// baseline (speedup 1.0000x reference)
#include <cuda_runtime.h>
#include <cstdint>

// VariableGroupNorm: x[N,C,H,W] fp32, ragged groups (channels contiguous per group).
// N=32, C=256, H=W=56, G=32. Group starts are multiples of 4 (sizes alternate 4/12),
// so a 4-channel chunk never crosses a group boundary.
// K1: 2048 uniform CTAs -> per-chunk (sum,sumsq) partials.
// K2: 2048 uniform CTAs -> gather 1-3 partials for the owning group, apply.

#define NB 32
#define CC 256
#define GG 32
#define HW 3136                 // 56*56
#define CHUNK_CH 4              // channels per chunk
#define CHUNKS_PER_N (CC / CHUNK_CH)   // 64
#define NV (CHUNK_CH * HW / 4)  // float4 per chunk = 3136
#define VGN_EPS 1e-5f
#define TPB 256

__device__ float2 d_partial[NB * CHUNKS_PER_N];   // (sum, sumsq) per (n, chunk)

// Decode group table from raw buffer (int32 or int64, defensively).
// Returns, for chunk-channel c0: group id g, group chunk range [cs, ce), group size.
__device__ __forceinline__ void decode_for_chunk(const void* __restrict__ gs_raw,
                                                 int c0, int& g, int& cs, int& ce,
                                                 int& gsize) {
    const int* p32 = (const int*)gs_raw;
    long long s32 = 0;
    #pragma unroll
    for (int i = 0; i < GG; i++) s32 += __ldg(&p32[i]);
    const bool is32 = (s32 == (long long)CC);
    const long long* p64 = (const long long*)gs_raw;

    int start = 0;
    g = 0; cs = 0; ce = 0; gsize = 0;
    #pragma unroll
    for (int i = 0; i < GG; i++) {
        const int sz = is32 ? __ldg(&p32[i]) : (int)__ldg(&p64[i]);
        if (c0 >= start && c0 < start + sz) {
            g = i;
            gsize = sz;
            cs = start / CHUNK_CH;
            ce = (start + sz) / CHUNK_CH;
        }
        start += sz;
    }
}

// ---- K1: per-chunk partial sums (pure read stream) ----
__global__ void __launch_bounds__(TPB)
vgn_stats_kernel(const float* __restrict__ x) {
    const int b = blockIdx.x;            // 0 .. 2047
    const int n = b >> 6;
    const int ck = b & (CHUNKS_PER_N - 1);
    const float4* __restrict__ px =
        (const float4*)(x + ((size_t)n * CC + (size_t)ck * CHUNK_CH) * HW);

    float s = 0.f, ss = 0.f;
    int i = threadIdx.x;
    #pragma unroll 1
    for (; i + 3 * TPB < NV; i += 4 * TPB) {
        float4 v[4];
        #pragma unroll
        for (int u = 0; u < 4; u++) v[u] = px[i + u * TPB];
        #pragma unroll
        for (int u = 0; u < 4; u++) {
            s  += (v[u].x + v[u].y) + (v[u].z + v[u].w);
            ss += v[u].x * v[u].x + v[u].y * v[u].y
                + v[u].z * v[u].z + v[u].w * v[u].w;
        }
    }
    if (i < NV) {                        // NV = 12*TPB + 64: one predicated tail
        const float4 v = px[i];
        s  += (v.x + v.y) + (v.z + v.w);
        ss += v.x * v.x + v.y * v.y + v.z * v.z + v.w * v.w;
    }

    #pragma unroll
    for (int o = 16; o > 0; o >>= 1) {
        s  += __shfl_xor_sync(0xFFFFFFFFu, s,  o);
        ss += __shfl_xor_sync(0xFFFFFFFFu, ss, o);
    }
    __shared__ float2 shw[TPB / 32];
    const int wid = threadIdx.x >> 5, lid = threadIdx.x & 31;
    if (lid == 0) shw[wid] = make_float2(s, ss);
    __syncthreads();
    if (threadIdx.x == 0) {
        float ts = 0.f, tss = 0.f;
        #pragma unroll
        for (int w = 0; w < TPB / 32; w++) { ts += shw[w].x; tss += shw[w].y; }
        d_partial[b] = make_float2(ts, tss);
    }
}

// ---- K2: gather group partials, normalize chunk ----
__global__ void __launch_bounds__(TPB)
vgn_apply_kernel(const float* __restrict__ x,
                 const float* __restrict__ gamma,
                 const float* __restrict__ beta,
                 float* __restrict__ out,
                 const void* __restrict__ gs_raw) {
    const int b = blockIdx.x;
    const int n = b >> 6;
    const int ck = b & (CHUNKS_PER_N - 1);
    const int c0 = ck * CHUNK_CH;

    // Thread 0 computes scale/shift, broadcasts via shared (avoids a 256-thread
    // replay burst on d_partial at kernel start).
    __shared__ float2 sh_prm;
    if (threadIdx.x == 0) {
        int g, cs, ce, gsize;
        decode_for_chunk(gs_raw, c0, g, cs, ce, gsize);
        float ts = 0.f, tss = 0.f;
        for (int c = cs; c < ce; c++) {
            const float2 p = d_partial[n * CHUNKS_PER_N + c];
            ts += p.x; tss += p.y;
        }
        const float inv   = 1.0f / (float)(gsize * HW);
        const float mean  = ts * inv;
        const float var   = tss * inv - mean * mean;
        const float sc    = __ldg(&gamma[g]) * rsqrtf(var + VGN_EPS);
        const float sf    = fmaf(-mean, sc, __ldg(&beta[g]));
        sh_prm = make_float2(sc, sf);
    }
    __syncthreads();
    const float sc = sh_prm.x;
    const float sf = sh_prm.y;

    const size_t base = ((size_t)n * CC + (size_t)c0) * HW;
    const float4* __restrict__ px = (const float4*)(x + base);
    float4* __restrict__ po       = (float4*)(out + base);

    int i = threadIdx.x;
    #pragma unroll 1
    for (; i + 3 * TPB < NV; i += 4 * TPB) {
        float4 v[4];
        #pragma unroll
        for (int u = 0; u < 4; u++) v[u] = __ldcs(px + i + u * TPB);
        #pragma unroll
        for (int u = 0; u < 4; u++) {
            v[u].x = fmaf(v[u].x, sc, sf);
            v[u].y = fmaf(v[u].y, sc, sf);
            v[u].z = fmaf(v[u].z, sc, sf);
            v[u].w = fmaf(v[u].w, sc, sf);
            __stcs(po + i + u * TPB, v[u]);
        }
    }
    if (i < NV) {
        float4 v = __ldcs(px + i);
        v.x = fmaf(v.x, sc, sf);
        v.y = fmaf(v.y, sc, sf);
        v.z = fmaf(v.z, sc, sf);
        v.w = fmaf(v.w, sc, sf);
        __stcs(po + i, v);
    }
}

extern "C" void kernel_launch(void* const* d_in, const int* in_sizes, int n_in,
                              void* d_out, int out_size) {
    const float* x     = (const float*)d_in[0];
    const float* gamma = (const float*)d_in[1];
    const float* beta  = (const float*)d_in[2];
    const void*  gsz   = d_in[3];
    float* out = (float*)d_out;

    vgn_stats_kernel<<<NB * CHUNKS_PER_N, TPB>>>(x);
    vgn_apply_kernel<<<NB * CHUNKS_PER_N, TPB>>>(x, gamma, beta, out, gsz);
}